// round 15
// baseline (speedup 1.0000x reference)
#include <cuda_runtime.h>
#include <cuda_fp16.h>

#define PP 32
#define SS 4
#define HH 256
#define WW 256
#define HW (HH*WW)          // 65536
#define NPIX (SS*HW)        // 262144
#define NOUT (PP*SS*HW)     // 8388608

__device__ uint2 g_data[(size_t)PP * SS * HW];   // 67 MB (L2-resident between passes)
__device__ uint4 g_bs[SS * HW];                  // 4 MB

static __device__ __forceinline__ unsigned pack2(float a, float b) {
    __half2 h = __floats2half2_rn(a, b);
    return *reinterpret_cast<unsigned*>(&h);
}
static __device__ __forceinline__ __half2 as_h2(unsigned u) {
    return *reinterpret_cast<__half2*>(&u);
}

// ---------------------------------------------------------------------------
// Pass 1 (R14 form + idx_base): chunked two-phase scan over half the pixels.
// ---------------------------------------------------------------------------
__global__ void __launch_bounds__(128, 7)
pass1_kernel(const float* __restrict__ colors,
             const float* __restrict__ alphas,
             const float* __restrict__ imgs_src,
             int idx_base)
{
    int idx = idx_base + blockIdx.x * blockDim.x + threadIdx.x;  // s*HW + pix

    float a2[16];
    #pragma unroll
    for (int i = 0; i < 16; i++)
        a2[i] = __ldcs(alphas + (size_t)(16 + i) * NPIX + idx);
    float t2 = 1.0f;
    #pragma unroll
    for (int i = 15; i >= 0; i--)
        t2 *= (1.0f - a2[i]);

    float ax = 0.f, ay = 0.f, az = 0.f;
    float p1x = 0.f, p1y = 0.f, p1z = 0.f;
    float p2x = 0.f, p2y = 0.f, p2z = 0.f;

    {
        float a1[16];
        #pragma unroll
        for (int i = 0; i < 16; i++)
            a1[i] = __ldcs(alphas + (size_t)i * NPIX + idx);

        float T1[16];
        {
            float t = t2;
            #pragma unroll
            for (int i = 15; i >= 0; i--) { T1[i] = t; t *= (1.0f - a1[i]); }
        }

        #pragma unroll
        for (int i = 0; i < 16; i++) {
            p2x = p1x; p2y = p1y; p2z = p1z;
            p1x = ax;  p1y = ay;  p1z = az;

            const float* c = colors + ((size_t)i * NPIX + idx) * 3;
            float ap  = a1[i];
            float cap = 1.0f - ap;
            ax = fmaf(ax, cap, __ldcs(c + 0) * ap);
            ay = fmaf(ay, cap, __ldcs(c + 1) * ap);
            az = fmaf(az, cap, __ldcs(c + 2) * ap);

            float sx, sy, sz;
            if (i == 0)      { sx = ax;  sy = ay;  sz = az;  }
            else if (i == 1) { sx = p1x; sy = p1y; sz = p1z; }
            else             { sx = p2x; sy = p2y; sz = p2z; }

            g_data[(size_t)i * NPIX + idx] =
                make_uint2(pack2(sx, sy), pack2(sz, T1[i]));
        }
    }

    {
        float T2[16];
        {
            float t = 1.0f;
            #pragma unroll
            for (int i = 15; i >= 0; i--) { T2[i] = t; t *= (1.0f - a2[i]); }
        }

        #pragma unroll
        for (int i = 0; i < 16; i++) {
            p2x = p1x; p2y = p1y; p2z = p1z;
            p1x = ax;  p1y = ay;  p1z = az;

            const float* c = colors + ((size_t)(16 + i) * NPIX + idx) * 3;
            float ap  = a2[i];
            float cap = 1.0f - ap;
            ax = fmaf(ax, cap, __ldcs(c + 0) * ap);
            ay = fmaf(ay, cap, __ldcs(c + 1) * ap);
            az = fmaf(az, cap, __ldcs(c + 2) * ap);

            g_data[(size_t)(16 + i) * NPIX + idx] =
                make_uint2(pack2(p2x, p2y), pack2(p2z, T2[i]));
        }
    }

    const float* sp = imgs_src + (size_t)idx * 3;
    float s0 = __ldg(sp + 0), s1 = __ldg(sp + 1), s2 = __ldg(sp + 2);
    g_bs[idx] = make_uint4(pack2(ax, ay), pack2(az, s0), pack2(s1, s2), 0u);
}

// ---------------------------------------------------------------------------
// Pass 2 (R14 form + s_base): covers planes x {s_base, s_base+1}.
// grid = 32 planes * 2 s * 64 blocks = 4096.
// ---------------------------------------------------------------------------
__global__ void __launch_bounds__(256, 8)
pass2_kernel(const float* __restrict__ mpi_planes,
             const float* __restrict__ pose_tgt,
             const float* __restrict__ intrins_src,
             const float* __restrict__ intrins_tgt,
             float* __restrict__ out,
             int s_base)
{
    __shared__ float w[12];

    int b    = blockIdx.x;
    int ps2  = b >> 6;                        // 0..63 : (p, s_half)
    int pix0 = ((b & 63) << 10) + threadIdx.x;
    int s    = s_base + (ps2 & 1);
    int p    = ps2 >> 1;
    int ps   = (p << 2) + s;

    if (threadIdx.x == 0) {
        float Kt[9];
        #pragma unroll
        for (int i = 0; i < 9; i++) Kt[i] = intrins_tgt[i];
        float det = Kt[0]*(Kt[4]*Kt[8]-Kt[5]*Kt[7])
                  - Kt[1]*(Kt[3]*Kt[8]-Kt[5]*Kt[6])
                  + Kt[2]*(Kt[3]*Kt[7]-Kt[4]*Kt[6]);
        float id = 1.0f / det;
        float inv[9];
        inv[0]=(Kt[4]*Kt[8]-Kt[5]*Kt[7])*id;
        inv[1]=(Kt[2]*Kt[7]-Kt[1]*Kt[8])*id;
        inv[2]=(Kt[1]*Kt[5]-Kt[2]*Kt[4])*id;
        inv[3]=(Kt[5]*Kt[6]-Kt[3]*Kt[8])*id;
        inv[4]=(Kt[0]*Kt[8]-Kt[2]*Kt[6])*id;
        inv[5]=(Kt[2]*Kt[3]-Kt[0]*Kt[5])*id;
        inv[6]=(Kt[3]*Kt[7]-Kt[4]*Kt[6])*id;
        inv[7]=(Kt[1]*Kt[6]-Kt[0]*Kt[7])*id;
        inv[8]=(Kt[0]*Kt[4]-Kt[1]*Kt[3])*id;

        const float* Ks   = intrins_src + s * 9;
        const float* pose = pose_tgt   + s * 16;

        float A[9], bb[3];
        #pragma unroll
        for (int i = 0; i < 3; i++) {
            #pragma unroll
            for (int j = 0; j < 3; j++) {
                float acc = 0.f;
                #pragma unroll
                for (int k = 0; k < 3; k++) acc += Ks[i*3+k] * pose[k*4+j];
                A[i*3+j] = acc;
            }
            float accb = 0.f;
            #pragma unroll
            for (int k = 0; k < 3; k++) accb += Ks[i*3+k] * pose[k*4+3];
            bb[i] = accb;
        }
        float d = mpi_planes[p];
        #pragma unroll
        for (int i = 0; i < 3; i++)
            #pragma unroll
            for (int j = 0; j < 3; j++) {
                float acc = 0.f;
                #pragma unroll
                for (int k = 0; k < 3; k++) acc += A[i*3+k] * inv[k*3+j];
                w[i*3+j] = acc * d;
            }
        w[9] = bb[0]; w[10] = bb[1]; w[11] = bb[2];
    }
    __syncthreads();

    const size_t basep = (size_t)ps * HW;
    const int    bases = s * HW;
    float*       op    = out + (size_t)ps * 10 * HW;

    const float fx  = (float)(pix0 & (WW - 1));
    const float fy0 = (float)(pix0 >> 8);

    float u0 = fmaf(w[0], fx, fmaf(w[1], fy0, w[2])) + w[9];
    float u1 = fmaf(w[3], fx, fmaf(w[4], fy0, w[5])) + w[10];
    float u2 = fmaf(w[6], fx, fmaf(w[7], fy0, w[8])) + w[11];

    #pragma unroll
    for (int k = 0; k < 4; k++) {
        float z  = u2 + 1e-10f;
        float rz = 1.0f / z;
        float ix = u0 * rz;
        float iy = u1 * rz;
        u0 += w[1]; u1 += w[4]; u2 += w[7];

        float x0f = floorf(ix), y0f = floorf(iy);
        float wx1 = ix - x0f, wy1 = iy - y0f;
        float wx0 = 1.0f - wx1, wy0 = 1.0f - wy1;

        int x0 = (int)x0f, y0i = (int)y0f;

        int xc0 = min(max(x0,     0), WW - 1);
        int xc1 = min(max(x0 + 1, 0), WW - 1);
        int yc0 = min(max(y0i,    0), HH - 1);
        int yc1 = min(max(y0i + 1, 0), HH - 1);
        bool vx0 = (x0 >= 0)   & (x0 <= WW - 1);
        bool vx1 = (x0 >= -1)  & (x0 <= WW - 2);
        bool vy0 = (y0i >= 0)  & (y0i <= HH - 1);
        bool vy1 = (y0i >= -1) & (y0i <= HH - 2);

        int   offs[4];
        float wgts[4];
        offs[0] = yc0 * WW + xc0;  wgts[0] = (vx0 & vy0) ? wx0 * wy0 : 0.f;
        offs[1] = yc0 * WW + xc1;  wgts[1] = (vx1 & vy0) ? wx1 * wy0 : 0.f;
        offs[2] = yc1 * WW + xc0;  wgts[2] = (vx0 & vy1) ? wx0 * wy1 : 0.f;
        offs[3] = yc1 * WW + xc1;  wgts[3] = (vx1 & vy1) ? wx1 * wy1 : 0.f;

        uint2 dU[4];
        uint4 bU[4];
        #pragma unroll
        for (int j = 0; j < 4; j++) {
            dU[j] = __ldg(&g_data[basep + offs[j]]);
            bU[j] = __ldg(&g_bs[bases + offs[j]]);
        }

        __half2 a0 = __float2half2_rn(0.f), a1 = a0, a2 = a0, a3 = a0, a4 = a0;
        #pragma unroll
        for (int j = 0; j < 4; j++) {
            __half2 hw = __float2half2_rn(wgts[j]);
            a0 = __hfma2(as_h2(dU[j].x), hw, a0);
            a1 = __hfma2(as_h2(dU[j].y), hw, a1);
            a2 = __hfma2(as_h2(bU[j].x), hw, a2);
            a3 = __hfma2(as_h2(bU[j].y), hw, a3);
            a4 = __hfma2(as_h2(bU[j].z), hw, a4);
        }

        int pix = pix0 + (k << 8);
        float2 f0 = __half22float2(a0);
        float2 f1 = __half22float2(a1);
        float2 f2 = __half22float2(a2);
        float2 f3 = __half22float2(a3);
        float2 f4 = __half22float2(a4);

        __stcs(op + 0*HW + pix, f1.y);   // T
        __stcs(op + 1*HW + pix, f0.x);   // acc.r
        __stcs(op + 2*HW + pix, f0.y);   // acc.g
        __stcs(op + 3*HW + pix, f1.x);   // acc.b
        __stcs(op + 4*HW + pix, f2.x);   // bro.r
        __stcs(op + 5*HW + pix, f2.y);   // bro.g
        __stcs(op + 6*HW + pix, f3.x);   // bro.b
        __stcs(op + 7*HW + pix, f3.y);   // src.r
        __stcs(op + 8*HW + pix, f4.x);   // src.g
        __stcs(op + 9*HW + pix, f4.y);   // src.b
    }
}

// ---------------------------------------------------------------------------
// Static-init side stream + events (host objects; created before any
// harness mem checkpoint; no device allocation in kernel_launch).
// ---------------------------------------------------------------------------
struct OverlapCtx {
    cudaStream_t s2;
    cudaEvent_t  evFork, evJoin;
    OverlapCtx() {
        cudaStreamCreateWithFlags(&s2, cudaStreamNonBlocking);
        cudaEventCreateWithFlags(&evFork, cudaEventDisableTiming);
        cudaEventCreateWithFlags(&evJoin, cudaEventDisableTiming);
    }
};
static OverlapCtx g_ctx;

// ---------------------------------------------------------------------------
extern "C" void kernel_launch(void* const* d_in, const int* in_sizes, int n_in,
                              void* d_out, int out_size)
{
    const float* colors      = (const float*)d_in[0];  // (P,S,H,W,3)
    const float* alphas      = (const float*)d_in[1];  // (P,S,H,W)
    const float* imgs_src    = (const float*)d_in[2];  // (S,H,W,3)
    const float* mpi_planes  = (const float*)d_in[3];  // (P,)
    const float* pose_tgt    = (const float*)d_in[4];  // (S,4,4)
    const float* intrins_src = (const float*)d_in[5];  // (S,3,3)
    const float* intrins_tgt = (const float*)d_in[6];  // (3,3)
    float* out = (float*)d_out;                        // (P,S,10,H,W)

    const int HALF_PIX = NPIX / 2;   // s = {0,1}

    // fork side stream from the capture (default) stream
    cudaEventRecord(g_ctx.evFork, 0);
    cudaStreamWaitEvent(g_ctx.s2, g_ctx.evFork, 0);

    // main stream: pass1 on s01, then pass2 on s01
    pass1_kernel<<<HALF_PIX / 128, 128>>>(colors, alphas, imgs_src, 0);

    // side stream: pass1 on s23 (independent), overlaps with p1a/p2a
    pass1_kernel<<<HALF_PIX / 128, 128, 0, g_ctx.s2>>>(colors, alphas, imgs_src, HALF_PIX);
    cudaEventRecord(g_ctx.evJoin, g_ctx.s2);

    pass2_kernel<<<4096, 256>>>(mpi_planes, pose_tgt, intrins_src, intrins_tgt, out, 0);

    // join: pass2 on s23 needs pass1(s23)
    cudaStreamWaitEvent(0, g_ctx.evJoin, 0);
    pass2_kernel<<<4096, 256>>>(mpi_planes, pose_tgt, intrins_src, intrins_tgt, out, 2);
}

// round 16
// speedup vs baseline: 1.0554x; 1.0554x over previous
#include <cuda_runtime.h>
#include <cuda_fp16.h>

#define PP 32
#define SS 4
#define HH 256
#define WW 256
#define HW (HH*WW)          // 65536
#define NPIX (SS*HW)        // 262144
#define NOUT (PP*SS*HW)     // 8388608

// Scratch per (p,s,pixel): two half2 = {acc.r,acc.g | acc.b,T}  (8 B)
// Default-policy writes -> L2-resident between passes (71 MB < 126 MB L2)
__device__ uint2 g_data[(size_t)PP * SS * HW];   // 67 MB
// Per (s,pixel), SoA: {bro.r,bro.g | bro.b,src.r} + {src.g,src.b}
__device__ uint2 g_bs2[SS * HW];                 // 2 MB
__device__ unsigned g_bs1[SS * HW];              // 1 MB

static __device__ __forceinline__ unsigned pack2(float a, float b) {
    __half2 h = __floats2half2_rn(a, b);
    return *reinterpret_cast<unsigned*>(&h);
}
static __device__ __forceinline__ __half2 as_h2(unsigned u) {
    return *reinterpret_cast<__half2*>(&u);
}

// ---------------------------------------------------------------------------
// Pass 1 (R14 form): chunked two-phase scan (16+16 planes).
// ---------------------------------------------------------------------------
__global__ void __launch_bounds__(128, 7)
pass1_kernel(const float* __restrict__ colors,
             const float* __restrict__ alphas,
             const float* __restrict__ imgs_src)
{
    int idx = blockIdx.x * blockDim.x + threadIdx.x;   // s*HW + pix
    if (idx >= NPIX) return;

    float a2[16];
    #pragma unroll
    for (int i = 0; i < 16; i++)
        a2[i] = __ldcs(alphas + (size_t)(16 + i) * NPIX + idx);
    float t2 = 1.0f;
    #pragma unroll
    for (int i = 15; i >= 0; i--)
        t2 *= (1.0f - a2[i]);

    float ax = 0.f, ay = 0.f, az = 0.f;
    float p1x = 0.f, p1y = 0.f, p1z = 0.f;
    float p2x = 0.f, p2y = 0.f, p2z = 0.f;

    {
        float a1[16];
        #pragma unroll
        for (int i = 0; i < 16; i++)
            a1[i] = __ldcs(alphas + (size_t)i * NPIX + idx);

        float T1[16];
        {
            float t = t2;
            #pragma unroll
            for (int i = 15; i >= 0; i--) { T1[i] = t; t *= (1.0f - a1[i]); }
        }

        #pragma unroll
        for (int i = 0; i < 16; i++) {
            p2x = p1x; p2y = p1y; p2z = p1z;
            p1x = ax;  p1y = ay;  p1z = az;

            const float* c = colors + ((size_t)i * NPIX + idx) * 3;
            float ap  = a1[i];
            float cap = 1.0f - ap;
            ax = fmaf(ax, cap, __ldcs(c + 0) * ap);
            ay = fmaf(ay, cap, __ldcs(c + 1) * ap);
            az = fmaf(az, cap, __ldcs(c + 2) * ap);

            float sx, sy, sz;
            if (i == 0)      { sx = ax;  sy = ay;  sz = az;  }
            else if (i == 1) { sx = p1x; sy = p1y; sz = p1z; }
            else             { sx = p2x; sy = p2y; sz = p2z; }

            g_data[(size_t)i * NPIX + idx] =
                make_uint2(pack2(sx, sy), pack2(sz, T1[i]));
        }
    }

    {
        float T2[16];
        {
            float t = 1.0f;
            #pragma unroll
            for (int i = 15; i >= 0; i--) { T2[i] = t; t *= (1.0f - a2[i]); }
        }

        #pragma unroll
        for (int i = 0; i < 16; i++) {
            p2x = p1x; p2y = p1y; p2z = p1z;
            p1x = ax;  p1y = ay;  p1z = az;

            const float* c = colors + ((size_t)(16 + i) * NPIX + idx) * 3;
            float ap  = a2[i];
            float cap = 1.0f - ap;
            ax = fmaf(ax, cap, __ldcs(c + 0) * ap);
            ay = fmaf(ay, cap, __ldcs(c + 1) * ap);
            az = fmaf(az, cap, __ldcs(c + 2) * ap);

            g_data[(size_t)(16 + i) * NPIX + idx] =
                make_uint2(pack2(p2x, p2y), pack2(p2z, T2[i]));
        }
    }

    const float* sp = imgs_src + (size_t)idx * 3;
    float s0 = __ldg(sp + 0), s1 = __ldg(sp + 1), s2 = __ldg(sp + 2);
    g_bs2[idx] = make_uint2(pack2(ax, ay), pack2(az, s0));
    g_bs1[idx] = pack2(s1, s2);
}

// ---------------------------------------------------------------------------
// Pass 2 (R14 form, g_bs SoA): branchless corners, per-pixel retire,
// 4 pixels per thread (stride 256), occ-8.
// ---------------------------------------------------------------------------
__global__ void __launch_bounds__(256, 8)
pass2_kernel(const float* __restrict__ mpi_planes,
             const float* __restrict__ pose_tgt,
             const float* __restrict__ intrins_src,
             const float* __restrict__ intrins_tgt,
             float* __restrict__ out)
{
    __shared__ float w[12];

    int b    = blockIdx.x;
    int ps   = b >> 6;                        // 64 blocks per (p,s)
    int pix0 = ((b & 63) << 10) + threadIdx.x;
    int s    = ps & (SS - 1);
    int p    = ps >> 2;

    if (threadIdx.x == 0) {
        float Kt[9];
        #pragma unroll
        for (int i = 0; i < 9; i++) Kt[i] = intrins_tgt[i];
        float det = Kt[0]*(Kt[4]*Kt[8]-Kt[5]*Kt[7])
                  - Kt[1]*(Kt[3]*Kt[8]-Kt[5]*Kt[6])
                  + Kt[2]*(Kt[3]*Kt[7]-Kt[4]*Kt[6]);
        float id = 1.0f / det;
        float inv[9];
        inv[0]=(Kt[4]*Kt[8]-Kt[5]*Kt[7])*id;
        inv[1]=(Kt[2]*Kt[7]-Kt[1]*Kt[8])*id;
        inv[2]=(Kt[1]*Kt[5]-Kt[2]*Kt[4])*id;
        inv[3]=(Kt[5]*Kt[6]-Kt[3]*Kt[8])*id;
        inv[4]=(Kt[0]*Kt[8]-Kt[2]*Kt[6])*id;
        inv[5]=(Kt[2]*Kt[3]-Kt[0]*Kt[5])*id;
        inv[6]=(Kt[3]*Kt[7]-Kt[4]*Kt[6])*id;
        inv[7]=(Kt[1]*Kt[6]-Kt[0]*Kt[7])*id;
        inv[8]=(Kt[0]*Kt[4]-Kt[1]*Kt[3])*id;

        const float* Ks   = intrins_src + s * 9;
        const float* pose = pose_tgt   + s * 16;

        float A[9], bb[3];
        #pragma unroll
        for (int i = 0; i < 3; i++) {
            #pragma unroll
            for (int j = 0; j < 3; j++) {
                float acc = 0.f;
                #pragma unroll
                for (int k = 0; k < 3; k++) acc += Ks[i*3+k] * pose[k*4+j];
                A[i*3+j] = acc;
            }
            float accb = 0.f;
            #pragma unroll
            for (int k = 0; k < 3; k++) accb += Ks[i*3+k] * pose[k*4+3];
            bb[i] = accb;
        }
        float d = mpi_planes[p];
        #pragma unroll
        for (int i = 0; i < 3; i++)
            #pragma unroll
            for (int j = 0; j < 3; j++) {
                float acc = 0.f;
                #pragma unroll
                for (int k = 0; k < 3; k++) acc += A[i*3+k] * inv[k*3+j];
                w[i*3+j] = acc * d;
            }
        w[9] = bb[0]; w[10] = bb[1]; w[11] = bb[2];
    }
    __syncthreads();

    const size_t basep = (size_t)ps * HW;
    const int    bases = s * HW;
    float*       op    = out + (size_t)ps * 10 * HW;

    const float fx  = (float)(pix0 & (WW - 1));
    const float fy0 = (float)(pix0 >> 8);

    float u0 = fmaf(w[0], fx, fmaf(w[1], fy0, w[2])) + w[9];
    float u1 = fmaf(w[3], fx, fmaf(w[4], fy0, w[5])) + w[10];
    float u2 = fmaf(w[6], fx, fmaf(w[7], fy0, w[8])) + w[11];

    #pragma unroll
    for (int k = 0; k < 4; k++) {
        float z  = u2 + 1e-10f;
        float rz = 1.0f / z;
        float ix = u0 * rz;
        float iy = u1 * rz;
        u0 += w[1]; u1 += w[4]; u2 += w[7];

        float x0f = floorf(ix), y0f = floorf(iy);
        float wx1 = ix - x0f, wy1 = iy - y0f;
        float wx0 = 1.0f - wx1, wy0 = 1.0f - wy1;

        int x0 = (int)x0f, y0i = (int)y0f;

        int xc0 = min(max(x0,     0), WW - 1);
        int xc1 = min(max(x0 + 1, 0), WW - 1);
        int yc0 = min(max(y0i,    0), HH - 1);
        int yc1 = min(max(y0i + 1, 0), HH - 1);
        bool vx0 = (x0 >= 0)   & (x0 <= WW - 1);
        bool vx1 = (x0 >= -1)  & (x0 <= WW - 2);
        bool vy0 = (y0i >= 0)  & (y0i <= HH - 1);
        bool vy1 = (y0i >= -1) & (y0i <= HH - 2);

        int   offs[4];
        float wgts[4];
        offs[0] = yc0 * WW + xc0;  wgts[0] = (vx0 & vy0) ? wx0 * wy0 : 0.f;
        offs[1] = yc0 * WW + xc1;  wgts[1] = (vx1 & vy0) ? wx1 * wy0 : 0.f;
        offs[2] = yc1 * WW + xc0;  wgts[2] = (vx0 & vy1) ? wx0 * wy1 : 0.f;
        offs[3] = yc1 * WW + xc1;  wgts[3] = (vx1 & vy1) ? wx1 * wy1 : 0.f;

        uint2    dU[4];
        uint2    b2[4];
        unsigned b1[4];
        #pragma unroll
        for (int j = 0; j < 4; j++) {
            dU[j] = __ldg(&g_data[basep + offs[j]]);
            b2[j] = __ldg(&g_bs2[bases + offs[j]]);
            b1[j] = __ldg(&g_bs1[bases + offs[j]]);
        }

        __half2 a0 = __float2half2_rn(0.f), a1 = a0, a2 = a0, a3 = a0, a4 = a0;
        #pragma unroll
        for (int j = 0; j < 4; j++) {
            __half2 hw = __float2half2_rn(wgts[j]);
            a0 = __hfma2(as_h2(dU[j].x), hw, a0);
            a1 = __hfma2(as_h2(dU[j].y), hw, a1);
            a2 = __hfma2(as_h2(b2[j].x), hw, a2);
            a3 = __hfma2(as_h2(b2[j].y), hw, a3);
            a4 = __hfma2(as_h2(b1[j]),   hw, a4);
        }

        int pix = pix0 + (k << 8);
        float2 f0 = __half22float2(a0);
        float2 f1 = __half22float2(a1);
        float2 f2 = __half22float2(a2);
        float2 f3 = __half22float2(a3);
        float2 f4 = __half22float2(a4);

        __stcs(op + 0*HW + pix, f1.y);   // T
        __stcs(op + 1*HW + pix, f0.x);   // acc.r
        __stcs(op + 2*HW + pix, f0.y);   // acc.g
        __stcs(op + 3*HW + pix, f1.x);   // acc.b
        __stcs(op + 4*HW + pix, f2.x);   // bro.r
        __stcs(op + 5*HW + pix, f2.y);   // bro.g
        __stcs(op + 6*HW + pix, f3.x);   // bro.b
        __stcs(op + 7*HW + pix, f3.y);   // src.r
        __stcs(op + 8*HW + pix, f4.x);   // src.g
        __stcs(op + 9*HW + pix, f4.y);   // src.b
    }
}

// ---------------------------------------------------------------------------
extern "C" void kernel_launch(void* const* d_in, const int* in_sizes, int n_in,
                              void* d_out, int out_size)
{
    const float* colors      = (const float*)d_in[0];  // (P,S,H,W,3)
    const float* alphas      = (const float*)d_in[1];  // (P,S,H,W)
    const float* imgs_src    = (const float*)d_in[2];  // (S,H,W,3)
    const float* mpi_planes  = (const float*)d_in[3];  // (P,)
    const float* pose_tgt    = (const float*)d_in[4];  // (S,4,4)
    const float* intrins_src = (const float*)d_in[5];  // (S,3,3)
    const float* intrins_tgt = (const float*)d_in[6];  // (3,3)
    float* out = (float*)d_out;                        // (P,S,10,H,W)

    pass1_kernel<<<NPIX / 128, 128>>>(colors, alphas, imgs_src);
    pass2_kernel<<<NOUT / 1024, 256>>>(mpi_planes, pose_tgt,
                                       intrins_src, intrins_tgt, out);
}